// round 1
// baseline (speedup 1.0000x reference)
#include <cuda_runtime.h>

#define C    10
#define C2   20
#define HW   128
#define TILE 16
#define HALO 18
#define HSZ  (HALO*HALO)   // 324

__device__ __forceinline__ float fsigmoid(float x) { return 1.0f / (1.0f + __expf(-x)); }
__device__ __forceinline__ float ftanh_fast(float x) { return 1.0f - 2.0f / (__expf(2.0f * x) + 1.0f); }

__global__ void __launch_bounds__(256, 2)
fused_tree_gru(const float* __restrict__ f_node,
               const float* __restrict__ h0g,
               const float* __restrict__ h1g,
               const float* __restrict__ att_w,
               const float* __restrict__ att_b,
               const float* __restrict__ rel_w,
               const float* __restrict__ bn_gamma,
               const float* __restrict__ bn_beta,
               const float* __restrict__ bn_mean,
               const float* __restrict__ bn_var,
               const float* __restrict__ gates_w,
               const float* __restrict__ gates_b,
               const float* __restrict__ can_w,
               const float* __restrict__ can_b,
               float* __restrict__ out_f,
               float* __restrict__ out_att)
{
    __shared__ float f_s [C*HSZ];
    __shared__ float h0_s[C*HSZ];
    __shared__ float h1_s[C*HSZ];
    __shared__ __align__(16) float wrel_s[C*9*C2];  // [(ci*9+k)*20 + 2*co + {0:wf,1:wh}], BN-scaled
    __shared__ float wg_s[C2*C2];
    __shared__ float wc_s[C*C2];
    __shared__ float attw_s[C2];
    __shared__ float gb_s[C2];
    __shared__ float cb_s[C];
    __shared__ float bias2_s[C];
    __shared__ float attb_s;

    const int tid = threadIdx.x;
    const int b   = blockIdx.z;
    const int tx0 = blockIdx.x * TILE;
    const int ty0 = blockIdx.y * TILE;

    // ---- stage weights into SMEM (BN folded into 3x3 conv weights) ----
    for (int i = tid; i < C*9*C2; i += 256) {
        int grp = i / C2;            // ci*9 + k
        int r   = i - grp*C2;
        int co  = r >> 1;
        int s   = r & 1;             // 0 -> f-half, 1 -> child-half
        int ci  = grp / 9;
        int k   = grp - ci*9;        // ky*3+kx
        float inv = bn_gamma[co] * rsqrtf(bn_var[co] + 1e-5f);
        int cin = s ? (C + ci) : ci;
        wrel_s[i] = rel_w[(co*C2 + cin)*9 + k] * inv;
    }
    for (int i = tid; i < C2*C2; i += 256) wg_s[i] = gates_w[i];
    for (int i = tid; i < C*C2;  i += 256) wc_s[i] = can_w[i];
    if (tid < C2) { attw_s[tid] = att_w[tid]; gb_s[tid] = gates_b[tid]; }
    if (tid < C) {
        cb_s[tid] = can_b[tid];
        float inv = bn_gamma[tid] * rsqrtf(bn_var[tid] + 1e-5f);
        bias2_s[tid] = bn_beta[tid] - bn_mean[tid] * inv;
    }
    if (tid == 0) attb_s = att_b[0];

    // ---- load haloed tiles (zero-pad at image edges) ----
    for (int i = tid; i < C*HSZ; i += 256) {
        int ci = i / HSZ;
        int p  = i - ci*HSZ;
        int ly = p / HALO, lx = p - ly*HALO;
        int gy = ty0 - 1 + ly, gx = tx0 - 1 + lx;
        bool ok = (gy >= 0) & (gy < HW) & (gx >= 0) & (gx < HW);
        long idx = ((long)(b*C + ci)*HW + gy)*HW + gx;
        f_s [i] = ok ? f_node[idx] : 0.f;
        h0_s[i] = ok ? h0g[idx]    : 0.f;
        h1_s[i] = ok ? h1g[idx]    : 0.f;
    }
    __syncthreads();

    // ---- attention: scale h tiles in place; write comp_att for center pixels ----
    for (int p = tid; p < HSZ; p += 256) {
        float v0[C], v1[C];
        float s = attb_s;
        #pragma unroll
        for (int ci = 0; ci < C; ++ci) {
            v0[ci] = h0_s[ci*HSZ + p];
            v1[ci] = h1_s[ci*HSZ + p];
            s += attw_s[ci]*v0[ci] + attw_s[C+ci]*v1[ci];
        }
        float a = fsigmoid(s);
        #pragma unroll
        for (int ci = 0; ci < C; ++ci) {
            h0_s[ci*HSZ + p] = v0[ci]*a;
            h1_s[ci*HSZ + p] = v1[ci]*a;
        }
        int ly = p / HALO, lx = p - ly*HALO;
        if (ly >= 1 && ly <= TILE && lx >= 1 && lx <= TILE)
            out_att[((long)b*HW + (ty0 + ly - 1))*HW + (tx0 + lx - 1)] = a;
    }
    __syncthreads();

    // ---- 3x3 conv: shared f-contribution + per-child contributions ----
    const int tx = tid & 15, ty = tid >> 4;
    const int base = ty*HALO + tx;
    float accf[C], a0[C], a1[C];
    #pragma unroll
    for (int co = 0; co < C; ++co) { accf[co] = 0.f; a0[co] = 0.f; a1[co] = 0.f; }

    for (int ci = 0; ci < C; ++ci) {
        const float* fb  = f_s  + ci*HSZ + base;
        const float* h0b = h0_s + ci*HSZ + base;
        const float* h1b = h1_s + ci*HSZ + base;
        const float4* wp = reinterpret_cast<const float4*>(wrel_s + ci*9*C2);
        #pragma unroll
        for (int k = 0; k < 9; ++k) {
            const int off = (k/3)*HALO + (k%3);
            float fv = fb[off], v0 = h0b[off], v1 = h1b[off];
            #pragma unroll
            for (int q = 0; q < 5; ++q) {
                float4 w = wp[k*5 + q];
                accf[2*q]   += w.x*fv;
                a0[2*q]     += w.y*v0;
                a1[2*q]     += w.y*v1;
                accf[2*q+1] += w.z*fv;
                a0[2*q+1]   += w.w*v0;
                a1[2*q+1]   += w.w*v1;
            }
        }
    }

    float comp_h[C], fc[C];
    #pragma unroll
    for (int co = 0; co < C; ++co) {
        float bz = bias2_s[co];
        comp_h[co] = fmaxf(accf[co] + a0[co] + bz, 0.f)
                   + fmaxf(accf[co] + a1[co] + bz, 0.f);
    }
    #pragma unroll
    for (int ci = 0; ci < C; ++ci)
        fc[ci] = f_s[ci*HSZ + (ty + 1)*HALO + (tx + 1)];

    // ---- ConvGRU gates (1x1) ----
    float r[C], u[C];
    #pragma unroll
    for (int co = 0; co < C2; ++co) {
        float g = gb_s[co];
        const float* w = wg_s + co*C2;
        #pragma unroll
        for (int ci = 0; ci < C; ++ci)
            g += w[ci]*comp_h[ci] + w[C+ci]*fc[ci];
        float sg = fsigmoid(g);
        if (co < C) r[co] = sg; else u[co - C] = sg;
    }
    float rf[C];
    #pragma unroll
    for (int ci = 0; ci < C; ++ci) rf[ci] = r[ci]*fc[ci];

    // ---- candidate + update, write output ----
    const int gy = ty0 + ty, gx = tx0 + tx;
    #pragma unroll
    for (int co = 0; co < C; ++co) {
        float g = cb_s[co];
        const float* w = wc_s + co*C2;
        #pragma unroll
        for (int ci = 0; ci < C; ++ci)
            g += w[ci]*comp_h[ci] + w[C+ci]*rf[ci];
        float t = ftanh_fast(g);
        float res = fc[co] + u[co]*(t - fc[co]);
        out_f[((long)(b*C + co)*HW + gy)*HW + gx] = res;
    }
}

extern "C" void kernel_launch(void* const* d_in, const int* in_sizes, int n_in,
                              void* d_out, int out_size) {
    (void)n_in; (void)out_size;
    const float* f_node   = (const float*)d_in[0];
    const float* h0       = (const float*)d_in[1];
    const float* h1       = (const float*)d_in[2];
    // d_in[3] = p_nodes (unused), d_in[4] = xf (unused)
    const float* att_w    = (const float*)d_in[5];
    const float* att_b    = (const float*)d_in[6];
    const float* rel_w    = (const float*)d_in[7];
    const float* bn_gamma = (const float*)d_in[8];
    const float* bn_beta  = (const float*)d_in[9];
    const float* bn_mean  = (const float*)d_in[10];
    const float* bn_var   = (const float*)d_in[11];
    const float* gates_w  = (const float*)d_in[12];
    const float* gates_b  = (const float*)d_in[13];
    const float* can_w    = (const float*)d_in[14];
    const float* can_b    = (const float*)d_in[15];

    int B = in_sizes[0] / (C * HW * HW);
    float* out_f   = (float*)d_out;
    float* out_att = out_f + (long)B * C * HW * HW;

    dim3 grid(HW / TILE, HW / TILE, B);
    fused_tree_gru<<<grid, 256>>>(f_node, h0, h1, att_w, att_b, rel_w,
                                  bn_gamma, bn_beta, bn_mean, bn_var,
                                  gates_w, gates_b, can_w, can_b,
                                  out_f, out_att);
}

// round 2
// speedup vs baseline: 1.2106x; 1.2106x over previous
#include <cuda_runtime.h>

#define C     10
#define C2    20
#define HW    128
#define TW    32
#define TH    16
#define HALOW 34
#define HALOH 18
#define HS    (HALOW*HALOH)   // 612

typedef unsigned long long ull;

// shared layout (floats)
#define OFF_F     0
#define OFF_H0    (C*HS)            // 6120
#define OFF_H1    (2*C*HS)          // 12240
#define OFF_WREL  (3*C*HS)          // 18360  (16B aligned: 73440B)
#define OFF_WG    (OFF_WREL + C*9*C2*2)   // +3600 = 21960
#define OFF_WC    (OFF_WG + C2*C2)        // 22360
#define OFF_ATTW  (OFF_WC + C*C2)         // 22560
#define OFF_GB    (OFF_ATTW + C2)         // 22580
#define OFF_CB    (OFF_GB + C2)           // 22600
#define OFF_B2    (OFF_CB + C)            // 22610
#define OFF_ATTB  (OFF_B2 + C)            // 22620
#define SMEM_FLOATS (OFF_ATTB + 1)
#define SMEM_BYTES (SMEM_FLOATS*4)

__device__ __forceinline__ float fsigmoid(float x) { return 1.0f / (1.0f + __expf(-x)); }
__device__ __forceinline__ float ftanh_fast(float x) { return 1.0f - 2.0f / (__expf(2.0f * x) + 1.0f); }

__device__ __forceinline__ ull pack2(float lo, float hi) {
    ull r; asm("mov.b64 %0, {%1,%2};" : "=l"(r) : "f"(lo), "f"(hi)); return r;
}
__device__ __forceinline__ void unpack2(ull v, float& lo, float& hi) {
    asm("mov.b64 {%0,%1}, %2;" : "=f"(lo), "=f"(hi) : "l"(v));
}
__device__ __forceinline__ void fma2(ull& acc, ull a, ull b) {
    asm("fma.rn.f32x2 %0, %1, %2, %0;" : "+l"(acc) : "l"(a), "l"(b));
}

__global__ void __launch_bounds__(256, 2)
fused_tree_gru(const float* __restrict__ f_node,
               const float* __restrict__ h0g,
               const float* __restrict__ h1g,
               const float* __restrict__ att_w,
               const float* __restrict__ att_b,
               const float* __restrict__ rel_w,
               const float* __restrict__ bn_gamma,
               const float* __restrict__ bn_beta,
               const float* __restrict__ bn_mean,
               const float* __restrict__ bn_var,
               const float* __restrict__ gates_w,
               const float* __restrict__ gates_b,
               const float* __restrict__ can_w,
               const float* __restrict__ can_b,
               float* __restrict__ out_f,
               float* __restrict__ out_att)
{
    extern __shared__ float sm[];
    float* f_s    = sm + OFF_F;
    float* h0_s   = sm + OFF_H0;
    float* h1_s   = sm + OFF_H1;
    float* wrel2  = sm + OFF_WREL;   // [(ci*9+k)*10+co]*4 -> {wf,wf,wh,wh} BN-scaled
    float* wg_s   = sm + OFF_WG;
    float* wc_s   = sm + OFF_WC;
    float* attw_s = sm + OFF_ATTW;
    float* gb_s   = sm + OFF_GB;
    float* cb_s   = sm + OFF_CB;
    float* b2_s   = sm + OFF_B2;
    float* attb_s = sm + OFF_ATTB;

    const int tid = threadIdx.x;
    const int b   = blockIdx.z;
    const int tx0 = blockIdx.x * TW;
    const int ty0 = blockIdx.y * TH;

    // ---- stage weights: 900 duplicated {wf,wf,wh,wh} entries, BN folded ----
    for (int e = tid; e < C*9*C; e += 256) {
        int co = e % C;
        int k  = (e / C) % 9;
        int ci = e / (9*C);
        float inv = bn_gamma[co] * rsqrtf(bn_var[co] + 1e-5f);
        float wf = rel_w[(co*C2 + ci)*9 + k] * inv;
        float wh = rel_w[(co*C2 + C + ci)*9 + k] * inv;
        float* d = wrel2 + ((ci*9 + k)*C + co)*4;
        d[0] = wf; d[1] = wf; d[2] = wh; d[3] = wh;
    }
    for (int i = tid; i < C2*C2; i += 256) wg_s[i] = gates_w[i];
    for (int i = tid; i < C*C2;  i += 256) wc_s[i] = can_w[i];
    if (tid < C2) { attw_s[tid] = att_w[tid]; gb_s[tid] = gates_b[tid]; }
    if (tid < C) {
        cb_s[tid] = can_b[tid];
        float inv = bn_gamma[tid] * rsqrtf(bn_var[tid] + 1e-5f);
        b2_s[tid] = bn_beta[tid] - bn_mean[tid] * inv;
    }
    if (tid == 0) attb_s[0] = att_b[0];

    // ---- load haloed tiles (zero-pad) ----
    for (int i = tid; i < C*HS; i += 256) {
        int ci = i / HS;
        int p  = i - ci*HS;
        int ly = p / HALOW, lx = p - ly*HALOW;
        int gy = ty0 - 1 + ly, gx = tx0 - 1 + lx;
        bool ok = (gy >= 0) & (gy < HW) & (gx >= 0) & (gx < HW);
        long idx = ((long)(b*C + ci)*HW + gy)*HW + gx;
        f_s [i] = ok ? f_node[idx] : 0.f;
        h0_s[i] = ok ? h0g[idx]    : 0.f;
        h1_s[i] = ok ? h1g[idx]    : 0.f;
    }
    __syncthreads();

    // ---- attention: scale h tiles in place; write comp_att at center ----
    {
        float ab = attb_s[0];
        for (int p = tid; p < HS; p += 256) {
            float v0[C], v1[C];
            float s = ab;
            #pragma unroll
            for (int ci = 0; ci < C; ++ci) {
                v0[ci] = h0_s[ci*HS + p];
                v1[ci] = h1_s[ci*HS + p];
                s += attw_s[ci]*v0[ci] + attw_s[C+ci]*v1[ci];
            }
            float a = fsigmoid(s);
            #pragma unroll
            for (int ci = 0; ci < C; ++ci) {
                h0_s[ci*HS + p] = v0[ci]*a;
                h1_s[ci*HS + p] = v1[ci]*a;
            }
            int ly = p / HALOW, lx = p - ly*HALOW;
            if (ly >= 1 && ly <= TH && lx >= 1 && lx <= TW)
                out_att[((long)b*HW + (ty0 + ly - 1))*HW + (tx0 + lx - 1)] = a;
        }
    }
    __syncthreads();

    // ---- 3x3 conv, 2 pixels/thread via f32x2 ----
    const int txp  = (tid & 15) * 2;   // 0..30
    const int ty   = tid >> 4;         // 0..15
    const int base = ty*HALOW + txp;

    ull accf[C], acc0[C], acc1[C];
    #pragma unroll
    for (int co = 0; co < C; ++co) { accf[co] = 0ull; acc0[co] = 0ull; acc1[co] = 0ull; }

    for (int ci = 0; ci < C; ++ci) {
        const float* fb  = f_s  + ci*HS + base;
        const float* h0b = h0_s + ci*HS + base;
        const float* h1b = h1_s + ci*HS + base;
        const ulonglong2* wci = reinterpret_cast<const ulonglong2*>(wrel2 + ci*9*C*4);
        #pragma unroll
        for (int r = 0; r < 3; ++r) {
            const int ro = r*HALOW;
            float f0 = fb[ro],  f1 = fb[ro+1],  f2 = fb[ro+2],  f3 = fb[ro+3];
            float g0 = h0b[ro], g1 = h0b[ro+1], g2 = h0b[ro+2], g3 = h0b[ro+3];
            float e0 = h1b[ro], e1 = h1b[ro+1], e2 = h1b[ro+2], e3 = h1b[ro+3];
            ull fp[3] = { pack2(f0,f1), pack2(f1,f2), pack2(f2,f3) };
            ull p0[3] = { pack2(g0,g1), pack2(g1,g2), pack2(g2,g3) };
            ull p1[3] = { pack2(e0,e1), pack2(e1,e2), pack2(e2,e3) };
            #pragma unroll
            for (int kx = 0; kx < 3; ++kx) {
                const ulonglong2* wk = wci + (r*3 + kx)*C;
                ull fv = fp[kx], v0 = p0[kx], v1 = p1[kx];
                #pragma unroll
                for (int co = 0; co < C; ++co) {
                    ulonglong2 w = wk[co];
                    fma2(accf[co], w.x, fv);
                    fma2(acc0[co], w.y, v0);
                    fma2(acc1[co], w.y, v1);
                }
            }
        }
    }

    // ---- epilogue: BN bias + ReLU + sum, then ConvGRU for 2 pixels ----
    float ch[2][C], fcv[2][C];
    #pragma unroll
    for (int co = 0; co < C; ++co) {
        float cf0, cf1, x00, x01, x10, x11;
        unpack2(accf[co], cf0, cf1);
        unpack2(acc0[co], x00, x01);
        unpack2(acc1[co], x10, x11);
        float bz = b2_s[co];
        ch[0][co] = fmaxf(cf0 + x00 + bz, 0.f) + fmaxf(cf0 + x10 + bz, 0.f);
        ch[1][co] = fmaxf(cf1 + x01 + bz, 0.f) + fmaxf(cf1 + x11 + bz, 0.f);
    }
    #pragma unroll
    for (int ci = 0; ci < C; ++ci) {
        const float* fc = f_s + ci*HS + (ty + 1)*HALOW + (txp + 1);
        fcv[0][ci] = fc[0];
        fcv[1][ci] = fc[1];
    }

    float rr[2][C], uu[2][C];
    #pragma unroll
    for (int co = 0; co < C2; ++co) {
        const float* w = wg_s + co*C2;
        float g0 = gb_s[co], g1 = g0;
        #pragma unroll
        for (int ci = 0; ci < C; ++ci) {
            float w1 = w[ci], w2 = w[C+ci];
            g0 += w1*ch[0][ci] + w2*fcv[0][ci];
            g1 += w1*ch[1][ci] + w2*fcv[1][ci];
        }
        float s0 = fsigmoid(g0), s1 = fsigmoid(g1);
        if (co < C) { rr[0][co] = s0; rr[1][co] = s1; }
        else        { uu[0][co-C] = s0; uu[1][co-C] = s1; }
    }
    float rf[2][C];
    #pragma unroll
    for (int ci = 0; ci < C; ++ci) {
        rf[0][ci] = rr[0][ci]*fcv[0][ci];
        rf[1][ci] = rr[1][ci]*fcv[1][ci];
    }

    const int gy = ty0 + ty, gx = tx0 + txp;
    #pragma unroll
    for (int co = 0; co < C; ++co) {
        const float* w = wc_s + co*C2;
        float g0 = cb_s[co], g1 = g0;
        #pragma unroll
        for (int ci = 0; ci < C; ++ci) {
            float w1 = w[ci], w2 = w[C+ci];
            g0 += w1*ch[0][ci] + w2*rf[0][ci];
            g1 += w1*ch[1][ci] + w2*rf[1][ci];
        }
        float t0 = ftanh_fast(g0), t1 = ftanh_fast(g1);
        float r0 = fcv[0][co] + uu[0][co]*(t0 - fcv[0][co]);
        float r1 = fcv[1][co] + uu[1][co]*(t1 - fcv[1][co]);
        long o = ((long)(b*C + co)*HW + gy)*HW + gx;
        out_f[o]   = r0;
        out_f[o+1] = r1;
    }
}

extern "C" void kernel_launch(void* const* d_in, const int* in_sizes, int n_in,
                              void* d_out, int out_size) {
    (void)n_in; (void)out_size;
    const float* f_node   = (const float*)d_in[0];
    const float* h0       = (const float*)d_in[1];
    const float* h1       = (const float*)d_in[2];
    // d_in[3] = p_nodes (unused), d_in[4] = xf (unused)
    const float* att_w    = (const float*)d_in[5];
    const float* att_b    = (const float*)d_in[6];
    const float* rel_w    = (const float*)d_in[7];
    const float* bn_gamma = (const float*)d_in[8];
    const float* bn_beta  = (const float*)d_in[9];
    const float* bn_mean  = (const float*)d_in[10];
    const float* bn_var   = (const float*)d_in[11];
    const float* gates_w  = (const float*)d_in[12];
    const float* gates_b  = (const float*)d_in[13];
    const float* can_w    = (const float*)d_in[14];
    const float* can_b    = (const float*)d_in[15];

    int B = in_sizes[0] / (C * HW * HW);
    float* out_f   = (float*)d_out;
    float* out_att = out_f + (long)B * C * HW * HW;

    static bool attr_set = false;
    if (!attr_set) {
        cudaFuncSetAttribute(fused_tree_gru,
                             cudaFuncAttributeMaxDynamicSharedMemorySize, SMEM_BYTES);
        attr_set = true;
    }

    dim3 grid(HW / TW, HW / TH, B);
    fused_tree_gru<<<grid, 256, SMEM_BYTES>>>(f_node, h0, h1, att_w, att_b, rel_w,
                                              bn_gamma, bn_beta, bn_mean, bn_var,
                                              gates_w, gates_b, can_w, can_b,
                                              out_f, out_att);
}